// round 16
// baseline (speedup 1.0000x reference)
#include <cuda_runtime.h>
#include <cuda_bf16.h>
#include <cstddef>
#include <cstdint>

#define H       128
#define NPL     100000
#define NTR     200000
#define NAR     50000
#define NT      350000
#define OFF_TR  100000
#define OFF_AR  300000
#define EPT     500000
#define ETA     200000
#define LBL     100000
#define GRID    152
#define NDIR    (2 * (EPT + ETA))

// ---------------- scratch ----------------
__device__ float g_x  [(size_t)NT * H];
__device__ float g_y  [(size_t)NT * H];
__device__ float g_inv[NT];
__device__ int   g_deg[NT];
__device__ int   g_rowptr[NT];
__device__ int   g_cur[NT];
__device__ int   g_adj[NDIR];
__device__ int   g_gctr;

// ---------------- generic helpers ----------------
__device__ __forceinline__ uint32_t smem_u32(const void* p) {
    uint32_t a;
    asm("{ .reg .u64 t; cvta.to.shared.u64 t, %1; cvt.u32.u64 %0, t; }" : "=r"(a) : "l"(p));
    return a;
}
#define SWZ(o) ((o) ^ (((o) >> 3) & 0x70))

// ---------------- mma.sync helpers ----------------
__device__ __forceinline__ void ldsm4(uint32_t& r0, uint32_t& r1, uint32_t& r2,
                                      uint32_t& r3, uint32_t addr) {
    asm volatile("ldmatrix.sync.aligned.m8n8.x4.shared.b16 {%0,%1,%2,%3}, [%4];"
                 : "=r"(r0), "=r"(r1), "=r"(r2), "=r"(r3) : "r"(addr));
}
__device__ __forceinline__ void mma16816(float* c, const uint32_t* a,
                                         uint32_t b0, uint32_t b1) {
    asm volatile(
        "mma.sync.aligned.m16n8k16.row.col.f32.bf16.bf16.f32 "
        "{%0,%1,%2,%3}, {%4,%5,%6,%7}, {%8,%9}, {%0,%1,%2,%3};"
        : "+f"(c[0]), "+f"(c[1]), "+f"(c[2]), "+f"(c[3])
        : "r"(a[0]), "r"(a[1]), "r"(a[2]), "r"(a[3]), "r"(b0), "r"(b1));
}

// fast truncation split: f -> hi (top 16 bits), lo = bf16_trunc(f - hi)
__device__ __forceinline__ void fsplit16(const float* f, uint32_t* hi, uint32_t* lo) {
    #pragma unroll
    for (int j = 0; j < 8; j++) {
        uint32_t u0 = __float_as_uint(f[2 * j]);
        uint32_t u1 = __float_as_uint(f[2 * j + 1]);
        hi[j] = __byte_perm(u0, u1, 0x7632);
        float r0 = f[2 * j]     - __uint_as_float(u0 & 0xFFFF0000u);
        float r1 = f[2 * j + 1] - __uint_as_float(u1 & 0xFFFF0000u);
        lo[j] = __byte_perm(__float_as_uint(r0), __float_as_uint(r1), 0x7632);
    }
}

// ---------------- small kernels ----------------
__global__ void k_embed2(const int* __restrict__ pl, const int* __restrict__ ar,
                         const float* __restrict__ plt, const float* __restrict__ art,
                         const float* __restrict__ tt, float* __restrict__ x)
{
    int t = blockIdx.x * blockDim.x + threadIdx.x;
    if (t < NPL * 32) {
        int i = t >> 5, c = t & 31;
        float4 v  = ((const float4*)(plt + (size_t)pl[i] * H))[c];
        float4 tv = ((const float4*)tt)[c];
        v.x += tv.x; v.y += tv.y; v.z += tv.z; v.w += tv.w;
        ((float4*)(x + (size_t)i * H))[c] = v;
    } else {
        t -= NPL * 32;
        if (t >= NAR * 32) return;
        int i = t >> 5, c = t & 31;
        float4 v  = ((const float4*)(art + (size_t)ar[i] * H))[c];
        float4 tv = ((const float4*)(tt + 2 * H))[c];
        v.x += tv.x; v.y += tv.y; v.z += tv.z; v.w += tv.w;
        ((float4*)(x + (size_t)(OFF_AR + i) * H))[c] = v;
    }
}

__global__ void k_deg(const int* __restrict__ sp, const int* __restrict__ dp,
                      const int* __restrict__ st, const int* __restrict__ dt)
{
    int e = blockIdx.x * blockDim.x + threadIdx.x;
    if (e == 0) g_gctr = 0;
    if (e < EPT) {
        atomicAdd(&g_deg[dp[e] + OFF_TR], 1);
        atomicAdd(&g_deg[sp[e]], 1);
    } else if (e < EPT + ETA) {
        int i = e - EPT;
        atomicAdd(&g_deg[dt[i] + OFF_AR], 1);
        atomicAdd(&g_deg[st[i] + OFF_TR], 1);
    }
}

__global__ void k_alloc()
{
    int i = blockIdx.x * blockDim.x + threadIdx.x;
    if (i < NT) {
        int d = g_deg[i];
        g_rowptr[i] = atomicAdd(&g_gctr, d);
        g_cur[i] = 0;
        g_inv[i] = 1.0f / fmaxf((float)d, 1.0f);
    }
}

__global__ void k_fill(const int* __restrict__ sp, const int* __restrict__ dp,
                       const int* __restrict__ st, const int* __restrict__ dt)
{
    int e = blockIdx.x * blockDim.x + threadIdx.x;
    int a, b;
    if (e < EPT) { a = sp[e];          b = dp[e] + OFF_TR; }
    else if (e < EPT + ETA) { int i = e - EPT; a = st[i] + OFF_TR; b = dt[i] + OFF_AR; }
    else return;
    int pa = atomicAdd(&g_cur[a], 1);
    g_adj[g_rowptr[a] + pa] = b;
    int pb = atomicAdd(&g_cur[b], 1);
    g_adj[g_rowptr[b] + pb] = a;
}

// ---------------- split-bf16 mma.sync GEMM with FUSED CSR gather -------------
// out[n][128] = act( concatK(mean_nbr(B), B) @ [Wl;Wr]^T + bias )   (DUAL)
//            or act( A32 @ W1^T + bias )                            (encode)
//            or logits via lrow/lcol concat + Wp2 dot               (GATHER+DOT)
// Tile 128x128; 16 warps 4x4; warp 32x32; s-outer fragment reuse (R13).
// K chunks of 64 double-buffered: stage(c+1 -> regs) || compute(c) || fsplit+STS.
// DUAL chunks 0-1: staging IS the CSR mean-gather (no agg roundtrip) -- each
// thread sums its 16-float segment over the node's neighbors, scales by inv.
template<int KK, bool DUALW, bool RELU, bool GATHER, bool DOT>
__global__ void __launch_bounds__(512, 1) k_mma(
    const float* __restrict__ A32, const float* __restrict__ B,
    const float* __restrict__ W1, const float* __restrict__ W2,
    const float* __restrict__ b1, const float* __restrict__ b2,
    const int* __restrict__ lrow, const int* __restrict__ lcol,
    const float* __restrict__ wp2, const float* __restrict__ bp2,
    float* __restrict__ out, int n)
{
    extern __shared__ char smraw[];
    const uint32_t raw  = smem_u32(smraw);
    const uint32_t base = (raw + 1023) & ~1023u;
    char* sb = smraw + (base - raw);

    constexpr int NCH = KK / 64;
    constexpr uint32_t AOFF = (uint32_t)NCH * 2 * 16384;
    constexpr uint32_t SOFF = AOFF + 2 * 32768;

    float* bs   = (float*)(sb + SOFF);
    float* w2s  = bs + 128;
    float* lsum = w2s + 128;

    const int tid = threadIdx.x;
    const int wid = tid >> 5, lane = tid & 31;

    // ---- stage W (hi/lo split, SW128 tiles), once per block ----
    for (int idx = tid; idx < 8 * KK; idx += 512) {
        int row = idx / (KK / 16);
        int kglob = (idx % (KK / 16)) * 16;
        const float* src;
        if (DUALW) src = (kglob < 128) ? (W1 + (size_t)row * 128 + kglob)
                                       : (W2 + (size_t)row * 128 + (kglob - 128));
        else       src = W1 + (size_t)row * KK + kglob;
        float f[16];
        *(float4*)(f + 0)  = ((const float4*)src)[0];
        *(float4*)(f + 4)  = ((const float4*)src)[1];
        *(float4*)(f + 8)  = ((const float4*)src)[2];
        *(float4*)(f + 12) = ((const float4*)src)[3];
        uint32_t hi[8], lo[8];
        fsplit16(f, hi, lo);
        int chunk = kglob >> 6;
        int kb = (kglob & 63) * 2;
        char* th = sb + (chunk * 2 + 0) * 16384;
        char* tl = sb + (chunk * 2 + 1) * 16384;
        uint32_t o0 = SWZ((uint32_t)(row * 128 + kb));
        uint32_t o1 = SWZ((uint32_t)(row * 128 + kb + 16));
        *(uint4*)(th + o0) = make_uint4(hi[0], hi[1], hi[2], hi[3]);
        *(uint4*)(th + o1) = make_uint4(hi[4], hi[5], hi[6], hi[7]);
        *(uint4*)(tl + o0) = make_uint4(lo[0], lo[1], lo[2], lo[3]);
        *(uint4*)(tl + o1) = make_uint4(lo[4], lo[5], lo[6], lo[7]);
    }
    for (int j = tid; j < 128; j += 512) {
        bs[j] = b1[j] + (b2 ? b2[j] : 0.0f);
        if (DOT) w2s[j] = wp2[j];
    }
    __syncthreads();

    const int wr = wid >> 2, wc = wid & 3;
    const uint32_t rowA  = (uint32_t)(lane & 15);
    const uint32_t kselA = (uint32_t)((lane >> 4) * 16);
    const uint32_t rowB  = (uint32_t)(((lane >> 4) * 8) + (lane & 7));
    const uint32_t kselB = (uint32_t)(((lane >> 3) & 1) * 16);
    const int srow = tid >> 2, skg = tid & 3;

    const int ntiles = (n + 127) >> 7;

    // stage chunk ch of tile at n0 into 16 regs
    auto ldreg = [&](int n0, int ch, float* f) {
        #pragma unroll
        for (int q = 0; q < 16; q++) f[q] = 0.f;
        int gn = n0 + srow;
        if (gn >= n) return;
        if (DUALW && ch < 2) {
            // fused CSR mean-gather: sum neighbor segments from B (=features)
            const int beg = g_rowptr[gn];
            const int d   = g_deg[gn];
            const int ro  = ch * 64 + skg * 16;
            float4 a0 = make_float4(0.f,0.f,0.f,0.f), a1 = a0, a2 = a0, a3 = a0;
            int j = 0;
            for (; j + 2 <= d; j += 2) {
                int s0 = g_adj[beg + j], s1 = g_adj[beg + j + 1];
                const float4* p0 = (const float4*)(B + (size_t)s0 * 128 + ro);
                const float4* p1 = (const float4*)(B + (size_t)s1 * 128 + ro);
                float4 u0 = p0[0], u1 = p0[1], u2 = p0[2], u3 = p0[3];
                float4 v0 = p1[0], v1 = p1[1], v2 = p1[2], v3 = p1[3];
                a0.x += u0.x + v0.x; a0.y += u0.y + v0.y; a0.z += u0.z + v0.z; a0.w += u0.w + v0.w;
                a1.x += u1.x + v1.x; a1.y += u1.y + v1.y; a1.z += u1.z + v1.z; a1.w += u1.w + v1.w;
                a2.x += u2.x + v2.x; a2.y += u2.y + v2.y; a2.z += u2.z + v2.z; a2.w += u2.w + v2.w;
                a3.x += u3.x + v3.x; a3.y += u3.y + v3.y; a3.z += u3.z + v3.z; a3.w += u3.w + v3.w;
            }
            if (j < d) {
                int s0 = g_adj[beg + j];
                const float4* p0 = (const float4*)(B + (size_t)s0 * 128 + ro);
                float4 u0 = p0[0], u1 = p0[1], u2 = p0[2], u3 = p0[3];
                a0.x += u0.x; a0.y += u0.y; a0.z += u0.z; a0.w += u0.w;
                a1.x += u1.x; a1.y += u1.y; a1.z += u1.z; a1.w += u1.w;
                a2.x += u2.x; a2.y += u2.y; a2.z += u2.z; a2.w += u2.w;
                a3.x += u3.x; a3.y += u3.y; a3.z += u3.z; a3.w += u3.w;
            }
            float iv = g_inv[gn];
            f[0]  = a0.x * iv; f[1]  = a0.y * iv; f[2]  = a0.z * iv; f[3]  = a0.w * iv;
            f[4]  = a1.x * iv; f[5]  = a1.y * iv; f[6]  = a1.z * iv; f[7]  = a1.w * iv;
            f[8]  = a2.x * iv; f[9]  = a2.y * iv; f[10] = a2.z * iv; f[11] = a2.w * iv;
            f[12] = a3.x * iv; f[13] = a3.y * iv; f[14] = a3.z * iv; f[15] = a3.w * iv;
        } else {
            const float* src;
            if (GATHER) {
                int r = (ch < 2) ? lrow[gn] : (OFF_TR + lcol[gn]);
                src = B + (size_t)r * 128 + (ch & 1) * 64 + skg * 16;
            } else if (DUALW) {
                src = B + (size_t)gn * 128 + (ch - 2) * 64 + skg * 16;
            } else {
                src = A32 + (size_t)gn * KK + ch * 64 + skg * 16;
            }
            *(float4*)(f + 0)  = ((const float4*)src)[0];
            *(float4*)(f + 4)  = ((const float4*)src)[1];
            *(float4*)(f + 8)  = ((const float4*)src)[2];
            *(float4*)(f + 12) = ((const float4*)src)[3];
        }
    };
    auto stchunk = [&](int buf, const float* f) {
        uint32_t hi[8], lo[8];
        fsplit16(f, hi, lo);
        char* dst = sb + AOFF + (uint32_t)buf * 32768;
        uint32_t o0 = SWZ((uint32_t)(srow * 128 + skg * 32));
        uint32_t o1 = SWZ((uint32_t)(srow * 128 + skg * 32 + 16));
        *(uint4*)(dst + o0) = make_uint4(hi[0], hi[1], hi[2], hi[3]);
        *(uint4*)(dst + o1) = make_uint4(hi[4], hi[5], hi[6], hi[7]);
        *(uint4*)(dst + 16384 + o0) = make_uint4(lo[0], lo[1], lo[2], lo[3]);
        *(uint4*)(dst + 16384 + o1) = make_uint4(lo[4], lo[5], lo[6], lo[7]);
    };

    for (int tile = blockIdx.x; tile < ntiles; tile += GRID) {
        const int n0 = tile << 7;

        float acc[2][4][4];
        #pragma unroll
        for (int mt = 0; mt < 2; mt++)
            #pragma unroll
            for (int nt = 0; nt < 4; nt++)
                #pragma unroll
                for (int q = 0; q < 4; q++) acc[mt][nt][q] = 0.f;
        if (DOT && tid < 128) lsum[tid] = 0.f;

        {
            float f[16];
            ldreg(n0, 0, f);
            stchunk(0, f);
        }
        __syncthreads();

        #pragma unroll 1
        for (int c = 0; c < NCH; c++) {
            float f[16];
            if (c + 1 < NCH) ldreg(n0, c + 1, f);

            const uint32_t ahi = base + AOFF + (uint32_t)(c & 1) * 32768;
            const uint32_t alo = ahi + 16384;
            const uint32_t whi = base + (uint32_t)(c * 2) * 16384;
            const uint32_t wlo = whi + 16384;

            #pragma unroll
            for (int s = 0; s < 4; s++) {
                uint32_t ah[2][4], al[2][4];
                #pragma unroll
                for (int mt = 0; mt < 2; mt++) {
                    uint32_t off = SWZ((uint32_t)((wr * 32 + mt * 16) + rowA) * 128
                                       + (uint32_t)(s * 32) + kselA);
                    ldsm4(ah[mt][0], ah[mt][1], ah[mt][2], ah[mt][3], ahi + off);
                    ldsm4(al[mt][0], al[mt][1], al[mt][2], al[mt][3], alo + off);
                }
                uint32_t bh[4][2], bl[4][2];
                #pragma unroll
                for (int bp = 0; bp < 2; bp++) {
                    uint32_t off = SWZ((uint32_t)((wc * 32 + bp * 16) + rowB) * 128
                                       + (uint32_t)(s * 32) + kselB);
                    uint32_t r0, r1, r2, r3;
                    ldsm4(r0, r1, r2, r3, whi + off);
                    bh[bp * 2][0] = r0;     bh[bp * 2][1] = r1;
                    bh[bp * 2 + 1][0] = r2; bh[bp * 2 + 1][1] = r3;
                    ldsm4(r0, r1, r2, r3, wlo + off);
                    bl[bp * 2][0] = r0;     bl[bp * 2][1] = r1;
                    bl[bp * 2 + 1][0] = r2; bl[bp * 2 + 1][1] = r3;
                }
                #pragma unroll
                for (int mt = 0; mt < 2; mt++)
                    #pragma unroll
                    for (int nt = 0; nt < 4; nt++) {
                        mma16816(acc[mt][nt], ah[mt], bh[nt][0], bh[nt][1]);
                        mma16816(acc[mt][nt], ah[mt], bl[nt][0], bl[nt][1]);
                        mma16816(acc[mt][nt], al[mt], bh[nt][0], bh[nt][1]);
                    }
            }

            if (c + 1 < NCH) stchunk((c + 1) & 1, f);
            __syncthreads();
        }

        const int lr = lane >> 2, lc2 = (lane & 3) * 2;
        if (DOT) {
            #pragma unroll
            for (int mt = 0; mt < 2; mt++) {
                float plo = 0.f, phi = 0.f;
                #pragma unroll
                for (int nt = 0; nt < 4; nt++) {
                    int col = wc * 32 + nt * 8 + lc2;
                    float w0 = w2s[col], w1 = w2s[col + 1];
                    float b0 = bs[col],  b1 = bs[col + 1];
                    plo += fmaxf(acc[mt][nt][0] + b0, 0.f) * w0
                         + fmaxf(acc[mt][nt][1] + b1, 0.f) * w1;
                    phi += fmaxf(acc[mt][nt][2] + b0, 0.f) * w0
                         + fmaxf(acc[mt][nt][3] + b1, 0.f) * w1;
                }
                plo += __shfl_xor_sync(0xffffffffu, plo, 1);
                plo += __shfl_xor_sync(0xffffffffu, plo, 2);
                phi += __shfl_xor_sync(0xffffffffu, phi, 1);
                phi += __shfl_xor_sync(0xffffffffu, phi, 2);
                if ((lane & 3) == 0) {
                    atomicAdd(&lsum[wr * 32 + mt * 16 + lr], plo);
                    atomicAdd(&lsum[wr * 32 + mt * 16 + lr + 8], phi);
                }
            }
            __syncthreads();
            if (tid < 128) {
                int gn = n0 + tid;
                if (gn < n) out[gn] = lsum[tid] + bp2[0];
            }
            __syncthreads();
        } else {
            #pragma unroll
            for (int mt = 0; mt < 2; mt++) {
                int r0 = n0 + wr * 32 + mt * 16 + lr;
                int r1 = r0 + 8;
                #pragma unroll
                for (int nt = 0; nt < 4; nt++) {
                    int col = wc * 32 + nt * 8 + lc2;
                    float b0 = bs[col], b1 = bs[col + 1];
                    float2 vlo = make_float2(acc[mt][nt][0] + b0, acc[mt][nt][1] + b1);
                    float2 vhi = make_float2(acc[mt][nt][2] + b0, acc[mt][nt][3] + b1);
                    if (RELU) {
                        vlo.x = fmaxf(vlo.x, 0.f); vlo.y = fmaxf(vlo.y, 0.f);
                        vhi.x = fmaxf(vhi.x, 0.f); vhi.y = fmaxf(vhi.y, 0.f);
                    }
                    if (r0 < n) *(float2*)(out + (size_t)r0 * 128 + col) = vlo;
                    if (r1 < n) *(float2*)(out + (size_t)r1 * 128 + col) = vhi;
                }
            }
        }
    }
}

// ---------------- launch ----------------
extern "C" void kernel_launch(void* const* d_in, const int* in_sizes, int n_in,
                              void* d_out, int out_size)
{
    const int*   pl_ids   = (const int*)  d_in[0];
    const int*   ar_ids   = (const int*)  d_in[1];
    const float* track_x  = (const float*)d_in[2];
    const int*   src_pt   = (const int*)  d_in[3];
    const int*   dst_pt   = (const int*)  d_in[4];
    const int*   src_ta   = (const int*)  d_in[5];
    const int*   dst_ta   = (const int*)  d_in[6];
    const int*   lab_row  = (const int*)  d_in[7];
    const int*   lab_col  = (const int*)  d_in[8];
    const float* pl_table = (const float*)d_in[9];
    const float* ar_table = (const float*)d_in[10];
    const float* Wtr      = (const float*)d_in[11];
    const float* btr      = (const float*)d_in[12];
    const float* type_tab = (const float*)d_in[13];
    const float* Wl0      = (const float*)d_in[14];
    const float* bl0      = (const float*)d_in[15];
    const float* Wr0      = (const float*)d_in[16];
    const float* Wl1      = (const float*)d_in[17];
    const float* bl1      = (const float*)d_in[18];
    const float* Wr1      = (const float*)d_in[19];
    const float* Wp1      = (const float*)d_in[20];
    const float* bp1      = (const float*)d_in[21];
    const float* Wp2      = (const float*)d_in[22];
    const float* bp2      = (const float*)d_in[23];
    float* out = (float*)d_out;

    float *x, *y; int* deg;
    cudaGetSymbolAddress((void**)&x,   g_x);
    cudaGetSymbolAddress((void**)&y,   g_y);
    cudaGetSymbolAddress((void**)&deg, g_deg);

    const int SMEM_K256 = 1024 + 8 * 16384 + 2 * 32768 + 1536;   // 199168
    const int SMEM_K128 = 1024 + 4 * 16384 + 2 * 32768 + 1536;   // 133632

    cudaFuncSetAttribute(k_mma<128, false, false, false, false>, cudaFuncAttributeMaxDynamicSharedMemorySize, SMEM_K128);
    cudaFuncSetAttribute(k_mma<256, true,  true,  false, false>, cudaFuncAttributeMaxDynamicSharedMemorySize, SMEM_K256);
    cudaFuncSetAttribute(k_mma<256, false, true,  true,  true >, cudaFuncAttributeMaxDynamicSharedMemorySize, SMEM_K256);

    // side stream: CSR build + pl/ar embeds (disjoint x regions from encode)
    cudaStream_t s2;
    cudaStreamCreateWithFlags(&s2, cudaStreamNonBlocking);
    cudaEvent_t eFork, eJoin;
    cudaEventCreateWithFlags(&eFork, cudaEventDisableTiming);
    cudaEventCreateWithFlags(&eJoin, cudaEventDisableTiming);

    cudaEventRecord(eFork, 0);
    cudaStreamWaitEvent(s2, eFork, 0);

    cudaMemsetAsync(deg, 0, (size_t)NT * sizeof(int), s2);
    k_deg<<<(EPT + ETA + 255) / 256, 256, 0, s2>>>(src_pt, dst_pt, src_ta, dst_ta);
    k_alloc<<<(NT + 255) / 256, 256, 0, s2>>>();
    k_fill<<<(EPT + ETA + 255) / 256, 256, 0, s2>>>(src_pt, dst_pt, src_ta, dst_ta);
    k_embed2<<<((NPL + NAR) * 32 + 255) / 256, 256, 0, s2>>>(pl_ids, ar_ids, pl_table,
                                                             ar_table, type_tab, x);
    cudaEventRecord(eJoin, s2);

    // main: encode GEMM (track features -> x[OFF_TR..])
    k_mma<128, false, false, false, false><<<GRID, 512, SMEM_K128>>>(
        track_x, nullptr, Wtr, nullptr, btr, type_tab + H,
        nullptr, nullptr, nullptr, nullptr, x + (size_t)OFF_TR * H, NTR);

    cudaStreamWaitEvent(0, eJoin, 0);

    // ---- layer 0: fused gather + dual GEMM (x -> y) ----
    k_mma<256, true, true, false, false><<<GRID, 512, SMEM_K256>>>(
        nullptr, x, Wl0, Wr0, bl0, nullptr,
        nullptr, nullptr, nullptr, nullptr, y, NT);

    // ---- layer 1: fused gather + dual GEMM (y -> x) ----
    k_mma<256, true, true, false, false><<<GRID, 512, SMEM_K256>>>(
        nullptr, y, Wl1, Wr1, bl1, nullptr,
        nullptr, nullptr, nullptr, nullptr, x, NT);

    // ---- predictor (gather + GEMM + dot fused) ----
    k_mma<256, false, true, true, true><<<GRID, 512, SMEM_K256>>>(
        nullptr, x, Wp1, nullptr, bp1, nullptr,
        lab_row, lab_col, Wp2, bp2, out, LBL);
}

// round 17
// speedup vs baseline: 1.1178x; 1.1178x over previous
#include <cuda_runtime.h>
#include <cuda_bf16.h>
#include <cstddef>
#include <cstdint>

#define H       128
#define NPL     100000
#define NTR     200000
#define NAR     50000
#define NT      350000
#define OFF_TR  100000
#define OFF_AR  300000
#define EPT     500000
#define ETA     200000
#define LBL     100000
#define GRID2   304
#define NDIR    (2 * (EPT + ETA))

// ---------------- scratch ----------------
__device__ float g_x  [(size_t)NT * H];
__device__ float g_y  [(size_t)NT * H];
__device__ float g_agg[(size_t)NT * H];
__device__ float g_inv[NT];
__device__ int   g_deg[NT];
__device__ int   g_rowptr[NT];
__device__ int   g_cur[NT];
__device__ int   g_adj[NDIR];
__device__ int   g_gctr;
// W planes: tile-byte layout (chunk-major, 128 rows x 64 k, unswizzled)
__device__ __align__(16) __nv_bfloat16 g_wEh[16384], g_wEl[16384];   // encode K=128
__device__ __align__(16) __nv_bfloat16 g_w0h[32768], g_w0l[32768];   // layer0 K=256
__device__ __align__(16) __nv_bfloat16 g_w1h[32768], g_w1l[32768];   // layer1 K=256
__device__ __align__(16) __nv_bfloat16 g_wPh[32768], g_wPl[32768];   // pred   K=256

// ---------------- generic helpers ----------------
__device__ __forceinline__ uint32_t smem_u32(const void* p) {
    uint32_t a;
    asm("{ .reg .u64 t; cvta.to.shared.u64 t, %1; cvt.u32.u64 %0, t; }" : "=r"(a) : "l"(p));
    return a;
}
#define SWZ(o) ((o) ^ (((o) >> 3) & 0x70))

__device__ __forceinline__ void cp16(void* smem_dst, const void* gsrc) {
    unsigned ds = (unsigned)__cvta_generic_to_shared(smem_dst);
    asm volatile("cp.async.cg.shared.global [%0], [%1], 16;" :: "r"(ds), "l"(gsrc) : "memory");
}

// ---------------- mma.sync helpers ----------------
__device__ __forceinline__ void ldsm4(uint32_t& r0, uint32_t& r1, uint32_t& r2,
                                      uint32_t& r3, uint32_t addr) {
    asm volatile("ldmatrix.sync.aligned.m8n8.x4.shared.b16 {%0,%1,%2,%3}, [%4];"
                 : "=r"(r0), "=r"(r1), "=r"(r2), "=r"(r3) : "r"(addr));
}
__device__ __forceinline__ void mma16816(float* c, const uint32_t* a,
                                         uint32_t b0, uint32_t b1) {
    asm volatile(
        "mma.sync.aligned.m16n8k16.row.col.f32.bf16.bf16.f32 "
        "{%0,%1,%2,%3}, {%4,%5,%6,%7}, {%8,%9}, {%0,%1,%2,%3};"
        : "+f"(c[0]), "+f"(c[1]), "+f"(c[2]), "+f"(c[3])
        : "r"(a[0]), "r"(a[1]), "r"(a[2]), "r"(a[3]), "r"(b0), "r"(b1));
}

// fast truncation split
__device__ __forceinline__ void fsplit16(const float* f, uint32_t* hi, uint32_t* lo) {
    #pragma unroll
    for (int j = 0; j < 8; j++) {
        uint32_t u0 = __float_as_uint(f[2 * j]);
        uint32_t u1 = __float_as_uint(f[2 * j + 1]);
        hi[j] = __byte_perm(u0, u1, 0x7632);
        float r0 = f[2 * j]     - __uint_as_float(u0 & 0xFFFF0000u);
        float r1 = f[2 * j + 1] - __uint_as_float(u1 & 0xFFFF0000u);
        lo[j] = __byte_perm(__float_as_uint(r0), __float_as_uint(r1), 0x7632);
    }
}

// ---------------- W pre-split: fp32 W -> bf16 hi/lo plane buffers -------------
template<int KK, bool DUALW>
__global__ void k_wsplit(const float* __restrict__ W1, const float* __restrict__ W2,
                         __nv_bfloat16* __restrict__ ph, __nv_bfloat16* __restrict__ pl)
{
    int idx = blockIdx.x * blockDim.x + threadIdx.x;
    if (idx >= 128 * (KK / 16)) return;
    int row = idx / (KK / 16);
    int kglob = (idx % (KK / 16)) * 16;
    const float* src;
    if (DUALW) src = (kglob < 128) ? (W1 + (size_t)row * 128 + kglob)
                                   : (W2 + (size_t)row * 128 + (kglob - 128));
    else       src = W1 + (size_t)row * KK + kglob;
    float f[16];
    *(float4*)(f + 0)  = ((const float4*)src)[0];
    *(float4*)(f + 4)  = ((const float4*)src)[1];
    *(float4*)(f + 8)  = ((const float4*)src)[2];
    *(float4*)(f + 12) = ((const float4*)src)[3];
    uint32_t hi[8], lo[8];
    fsplit16(f, hi, lo);
    size_t o = (size_t)(kglob >> 6) * 8192 + row * 64 + (kglob & 63);
    *(uint4*)(ph + o)     = make_uint4(hi[0], hi[1], hi[2], hi[3]);
    *(uint4*)(ph + o + 8) = make_uint4(hi[4], hi[5], hi[6], hi[7]);
    *(uint4*)(pl + o)     = make_uint4(lo[0], lo[1], lo[2], lo[3]);
    *(uint4*)(pl + o + 8) = make_uint4(lo[4], lo[5], lo[6], lo[7]);
}

// ---------------- small kernels ----------------
__global__ void k_embed2(const int* __restrict__ pl, const int* __restrict__ ar,
                         const float* __restrict__ plt, const float* __restrict__ art,
                         const float* __restrict__ tt, float* __restrict__ x)
{
    int t = blockIdx.x * blockDim.x + threadIdx.x;
    if (t < NPL * 32) {
        int i = t >> 5, c = t & 31;
        float4 v  = ((const float4*)(plt + (size_t)pl[i] * H))[c];
        float4 tv = ((const float4*)tt)[c];
        v.x += tv.x; v.y += tv.y; v.z += tv.z; v.w += tv.w;
        ((float4*)(x + (size_t)i * H))[c] = v;
    } else {
        t -= NPL * 32;
        if (t >= NAR * 32) return;
        int i = t >> 5, c = t & 31;
        float4 v  = ((const float4*)(art + (size_t)ar[i] * H))[c];
        float4 tv = ((const float4*)(tt + 2 * H))[c];
        v.x += tv.x; v.y += tv.y; v.z += tv.z; v.w += tv.w;
        ((float4*)(x + (size_t)(OFF_AR + i) * H))[c] = v;
    }
}

__global__ void k_deg(const int* __restrict__ sp, const int* __restrict__ dp,
                      const int* __restrict__ st, const int* __restrict__ dt)
{
    int e = blockIdx.x * blockDim.x + threadIdx.x;
    if (e == 0) g_gctr = 0;
    if (e < EPT) {
        atomicAdd(&g_deg[dp[e] + OFF_TR], 1);
        atomicAdd(&g_deg[sp[e]], 1);
    } else if (e < EPT + ETA) {
        int i = e - EPT;
        atomicAdd(&g_deg[dt[i] + OFF_AR], 1);
        atomicAdd(&g_deg[st[i] + OFF_TR], 1);
    }
}

__global__ void k_alloc()
{
    int i = blockIdx.x * blockDim.x + threadIdx.x;
    if (i < NT) {
        int d = g_deg[i];
        g_rowptr[i] = atomicAdd(&g_gctr, d);
        g_cur[i] = 0;
        g_inv[i] = 1.0f / fmaxf((float)d, 1.0f);
    }
}

__global__ void k_fill(const int* __restrict__ sp, const int* __restrict__ dp,
                       const int* __restrict__ st, const int* __restrict__ dt)
{
    int e = blockIdx.x * blockDim.x + threadIdx.x;
    int a, b;
    if (e < EPT) { a = sp[e];          b = dp[e] + OFF_TR; }
    else if (e < EPT + ETA) { int i = e - EPT; a = st[i] + OFF_TR; b = dt[i] + OFF_AR; }
    else return;
    int pa = atomicAdd(&g_cur[a], 1);
    g_adj[g_rowptr[a] + pa] = b;
    int pb = atomicAdd(&g_cur[b], 1);
    g_adj[g_rowptr[b] + pb] = a;
}

// CSR mean-gather: warp per node; lane owns float4 chunk; 8-way MLP unroll
__global__ void k_gather(const float* __restrict__ x, float* __restrict__ agg)
{
    int node = blockIdx.x * 8 + (threadIdx.x >> 5);
    if (node >= NT) return;
    int lane = threadIdx.x & 31;
    const int beg = g_rowptr[node];
    const int d   = g_deg[node];
    const float4* x4 = (const float4*)x;
    float4 acc = make_float4(0.f, 0.f, 0.f, 0.f);
    int j = 0;
    for (; j + 8 <= d; j += 8) {
        float4 v[8];
        #pragma unroll
        for (int q = 0; q < 8; q++) {
            int s = g_adj[beg + j + q];
            v[q] = x4[(size_t)s * 32 + lane];
        }
        #pragma unroll
        for (int q = 0; q < 8; q++) {
            acc.x += v[q].x; acc.y += v[q].y; acc.z += v[q].z; acc.w += v[q].w;
        }
    }
    for (; j < d; j++) {
        int s = g_adj[beg + j];
        float4 v = x4[(size_t)s * 32 + lane];
        acc.x += v.x; acc.y += v.y; acc.z += v.z; acc.w += v.w;
    }
    float iv = g_inv[node];
    acc.x *= iv; acc.y *= iv; acc.z *= iv; acc.w *= iv;
    ((float4*)agg)[(size_t)node * 32 + lane] = acc;
}

// ---------------- 2-CTA/SM split-bf16 mma.sync GEMM ----------------
// out[n][128] = act( concatK(A, B) @ W^T + bias ), K = 64*NCH.
// 256 threads, 8 warps (2x4), 64-node tiles, warp tile 32x32.
// W streamed per chunk from pre-split global planes via cp.async (dbl-buffered
// 2x32KB); A staged fp32->fsplit->STS (dbl-buffered 2x16KB). ~100KB smem ->
// 2 CTAs/SM: one CTA's barriers/staging hide under the other's MMA stream.
// GATHER: rows via lrow/lcol. DOT: Wp2 logits epilogue.
template<int KK, bool DUALA, bool RELU, bool GATHER, bool DOT>
__global__ void __launch_bounds__(256, 2) k_mma(
    const float* __restrict__ A32, const float* __restrict__ B,
    const __nv_bfloat16* __restrict__ wph, const __nv_bfloat16* __restrict__ wpl,
    const float* __restrict__ b1, const float* __restrict__ b2,
    const int* __restrict__ lrow, const int* __restrict__ lcol,
    const float* __restrict__ wp2, const float* __restrict__ bp2,
    float* __restrict__ out, int n)
{
    extern __shared__ char smraw[];
    const uint32_t raw  = smem_u32(smraw);
    const uint32_t base = (raw + 1023) & ~1023u;
    char* sb = smraw + (base - raw);

    constexpr int NCH = KK / 64;
    constexpr uint32_t AOFF = 65536;          // after 2 x 32KB W buffers
    constexpr uint32_t SOFF = AOFF + 32768;   // after 2 x 16KB A buffers

    float* bs   = (float*)(sb + SOFF);
    float* w2s  = bs + 128;
    float* lsum = w2s + 128;                  // 64

    const int tid = threadIdx.x;
    const int wid = tid >> 5, lane = tid & 31;

    for (int j = tid; j < 128; j += 256) {
        bs[j] = b1[j] + (b2 ? b2[j] : 0.0f);
        if (DOT) w2s[j] = wp2[j];
    }
    __syncthreads();

    const int wr = wid >> 2, wc = wid & 3;        // 2x4 warp grid
    const uint32_t rowA  = (uint32_t)(lane & 15);
    const uint32_t kselA = (uint32_t)((lane >> 4) * 16);
    const uint32_t rowB  = (uint32_t)(((lane >> 4) * 8) + (lane & 7));
    const uint32_t kselB = (uint32_t)(((lane >> 3) & 1) * 16);
    const int srow = tid >> 2, skg = tid & 3;     // staging: row 0..63, kgroup 0..3

    const int ntiles = (n + 63) >> 6;

    // cp.async W chunk tiles (hi+lo, 32KB) into wbuf (c&1)
    auto issueW = [&](int c) {
        if (c < NCH) {
            char* dst = sb + (uint32_t)(c & 1) * 32768;
            const char* srch = (const char*)(wph + (size_t)c * 8192);
            const char* srcl = (const char*)(wpl + (size_t)c * 8192);
            #pragma unroll
            for (int i = 0; i < 4; i++) {
                int elem = tid + i * 256;          // 0..1023
                uint32_t o = (uint32_t)((elem >> 3) * 128 + (elem & 7) * 16);
                cp16(dst + SWZ(o),         srch + o);
                cp16(dst + 16384 + SWZ(o), srcl + o);
            }
        }
        asm volatile("cp.async.commit_group;" ::: "memory");
    };

    auto ldreg = [&](int n0, int ch, float* f) {
        #pragma unroll
        for (int q = 0; q < 16; q++) f[q] = 0.f;
        int gn = n0 + srow;
        if (gn < n) {
            const float* src;
            if (GATHER) {
                int r = (ch < 2) ? lrow[gn] : (OFF_TR + lcol[gn]);
                src = B + (size_t)r * 128 + (ch & 1) * 64 + skg * 16;
            } else if (DUALA) {
                src = (ch < 2) ? (A32 + (size_t)gn * 128 + ch * 64 + skg * 16)
                               : (B + (size_t)gn * 128 + (ch - 2) * 64 + skg * 16);
            } else {
                src = A32 + (size_t)gn * KK + ch * 64 + skg * 16;
            }
            *(float4*)(f + 0)  = ((const float4*)src)[0];
            *(float4*)(f + 4)  = ((const float4*)src)[1];
            *(float4*)(f + 8)  = ((const float4*)src)[2];
            *(float4*)(f + 12) = ((const float4*)src)[3];
        }
    };
    auto stchunk = [&](int buf, const float* f) {
        uint32_t hi[8], lo[8];
        fsplit16(f, hi, lo);
        char* dst = sb + AOFF + (uint32_t)buf * 16384;
        uint32_t o0 = SWZ((uint32_t)(srow * 128 + skg * 32));
        uint32_t o1 = SWZ((uint32_t)(srow * 128 + skg * 32 + 16));
        *(uint4*)(dst + o0) = make_uint4(hi[0], hi[1], hi[2], hi[3]);
        *(uint4*)(dst + o1) = make_uint4(hi[4], hi[5], hi[6], hi[7]);
        *(uint4*)(dst + 8192 + o0) = make_uint4(lo[0], lo[1], lo[2], lo[3]);
        *(uint4*)(dst + 8192 + o1) = make_uint4(lo[4], lo[5], lo[6], lo[7]);
    };

    float acc[2][4][4];

    auto compute = [&](int c) {
        const uint32_t whi = base + (uint32_t)(c & 1) * 32768;
        const uint32_t wlo = whi + 16384;
        const uint32_t ahi = base + AOFF + (uint32_t)(c & 1) * 16384;
        const uint32_t alo = ahi + 8192;
        #pragma unroll
        for (int s = 0; s < 4; s++) {
            uint32_t ah[2][4], al[2][4];
            #pragma unroll
            for (int mt = 0; mt < 2; mt++) {
                uint32_t off = SWZ((uint32_t)((wr * 32 + mt * 16) + rowA) * 128
                                   + (uint32_t)(s * 32) + kselA);
                ldsm4(ah[mt][0], ah[mt][1], ah[mt][2], ah[mt][3], ahi + off);
                ldsm4(al[mt][0], al[mt][1], al[mt][2], al[mt][3], alo + off);
            }
            uint32_t bh[4][2], bl[4][2];
            #pragma unroll
            for (int bp = 0; bp < 2; bp++) {
                uint32_t off = SWZ((uint32_t)((wc * 32 + bp * 16) + rowB) * 128
                                   + (uint32_t)(s * 32) + kselB);
                uint32_t r0, r1, r2, r3;
                ldsm4(r0, r1, r2, r3, whi + off);
                bh[bp * 2][0] = r0;     bh[bp * 2][1] = r1;
                bh[bp * 2 + 1][0] = r2; bh[bp * 2 + 1][1] = r3;
                ldsm4(r0, r1, r2, r3, wlo + off);
                bl[bp * 2][0] = r0;     bl[bp * 2][1] = r1;
                bl[bp * 2 + 1][0] = r2; bl[bp * 2 + 1][1] = r3;
            }
            #pragma unroll
            for (int mt = 0; mt < 2; mt++)
                #pragma unroll
                for (int nt = 0; nt < 4; nt++) {
                    mma16816(acc[mt][nt], ah[mt], bh[nt][0], bh[nt][1]);
                    mma16816(acc[mt][nt], ah[mt], bl[nt][0], bl[nt][1]);
                    mma16816(acc[mt][nt], al[mt], bh[nt][0], bh[nt][1]);
                }
        }
    };

    for (int tile = blockIdx.x; tile < ntiles; tile += GRID2) {
        const int n0 = tile << 6;

        #pragma unroll
        for (int mt = 0; mt < 2; mt++)
            #pragma unroll
            for (int nt = 0; nt < 4; nt++)
                #pragma unroll
                for (int q = 0; q < 4; q++) acc[mt][nt][q] = 0.f;
        if (DOT && tid < 64) lsum[tid] = 0.f;

        // prologue: W(0) async + A(0) staged
        issueW(0);
        {
            float f[16];
            ldreg(n0, 0, f);
            stchunk(0, f);
        }
        asm volatile("cp.async.wait_group 0;" ::: "memory");
        __syncthreads();

        #pragma unroll 1
        for (int c = 0; c < NCH; c++) {
            float f[16];
            if (c + 1 < NCH) {
                issueW(c + 1);
                ldreg(n0, c + 1, f);
            }
            compute(c);
            if (c + 1 < NCH) stchunk((c + 1) & 1, f);
            asm volatile("cp.async.wait_group 0;" ::: "memory");
            __syncthreads();
        }

        // ---- epilogue ----
        const int lr = lane >> 2, lc2 = (lane & 3) * 2;
        if (DOT) {
            #pragma unroll
            for (int mt = 0; mt < 2; mt++) {
                float plo = 0.f, phi = 0.f;
                #pragma unroll
                for (int nt = 0; nt < 4; nt++) {
                    int col = wc * 32 + nt * 8 + lc2;
                    float w0 = w2s[col], w1 = w2s[col + 1];
                    float b0 = bs[col],  b1 = bs[col + 1];
                    plo += fmaxf(acc[mt][nt][0] + b0, 0.f) * w0
                         + fmaxf(acc[mt][nt][1] + b1, 0.f) * w1;
                    phi += fmaxf(acc[mt][nt][2] + b0, 0.f) * w0
                         + fmaxf(acc[mt][nt][3] + b1, 0.f) * w1;
                }
                plo += __shfl_xor_sync(0xffffffffu, plo, 1);
                plo += __shfl_xor_sync(0xffffffffu, plo, 2);
                phi += __shfl_xor_sync(0xffffffffu, phi, 1);
                phi += __shfl_xor_sync(0xffffffffu, phi, 2);
                if ((lane & 3) == 0) {
                    atomicAdd(&lsum[wr * 32 + mt * 16 + lr], plo);
                    atomicAdd(&lsum[wr * 32 + mt * 16 + lr + 8], phi);
                }
            }
            __syncthreads();
            if (tid < 64) {
                int gn = n0 + tid;
                if (gn < n) out[gn] = lsum[tid] + bp2[0];
            }
            __syncthreads();
        } else {
            #pragma unroll
            for (int mt = 0; mt < 2; mt++) {
                int r0 = n0 + wr * 32 + mt * 16 + lr;
                int r1 = r0 + 8;
                #pragma unroll
                for (int nt = 0; nt < 4; nt++) {
                    int col = wc * 32 + nt * 8 + lc2;
                    float b0 = bs[col], b1 = bs[col + 1];
                    float2 vlo = make_float2(acc[mt][nt][0] + b0, acc[mt][nt][1] + b1);
                    float2 vhi = make_float2(acc[mt][nt][2] + b0, acc[mt][nt][3] + b1);
                    if (RELU) {
                        vlo.x = fmaxf(vlo.x, 0.f); vlo.y = fmaxf(vlo.y, 0.f);
                        vhi.x = fmaxf(vhi.x, 0.f); vhi.y = fmaxf(vhi.y, 0.f);
                    }
                    if (r0 < n) *(float2*)(out + (size_t)r0 * 128 + col) = vlo;
                    if (r1 < n) *(float2*)(out + (size_t)r1 * 128 + col) = vhi;
                }
            }
        }
    }
}

// ---------------- launch ----------------
extern "C" void kernel_launch(void* const* d_in, const int* in_sizes, int n_in,
                              void* d_out, int out_size)
{
    const int*   pl_ids   = (const int*)  d_in[0];
    const int*   ar_ids   = (const int*)  d_in[1];
    const float* track_x  = (const float*)d_in[2];
    const int*   src_pt   = (const int*)  d_in[3];
    const int*   dst_pt   = (const int*)  d_in[4];
    const int*   src_ta   = (const int*)  d_in[5];
    const int*   dst_ta   = (const int*)  d_in[6];
    const int*   lab_row  = (const int*)  d_in[7];
    const int*   lab_col  = (const int*)  d_in[8];
    const float* pl_table = (const float*)d_in[9];
    const float* ar_table = (const float*)d_in[10];
    const float* Wtr      = (const float*)d_in[11];
    const float* btr      = (const float*)d_in[12];
    const float* type_tab = (const float*)d_in[13];
    const float* Wl0      = (const float*)d_in[14];
    const float* bl0      = (const float*)d_in[15];
    const float* Wr0      = (const float*)d_in[16];
    const float* Wl1      = (const float*)d_in[17];
    const float* bl1      = (const float*)d_in[18];
    const float* Wr1      = (const float*)d_in[19];
    const float* Wp1      = (const float*)d_in[20];
    const float* bp1      = (const float*)d_in[21];
    const float* Wp2      = (const float*)d_in[22];
    const float* bp2      = (const float*)d_in[23];
    float* out = (float*)d_out;

    float *x, *y, *agg; int* deg;
    __nv_bfloat16 *wEh, *wEl, *w0h, *w0l, *w1h, *w1l, *wPh, *wPl;
    cudaGetSymbolAddress((void**)&x,   g_x);
    cudaGetSymbolAddress((void**)&y,   g_y);
    cudaGetSymbolAddress((void**)&agg, g_agg);
    cudaGetSymbolAddress((void**)&deg, g_deg);
    cudaGetSymbolAddress((void**)&wEh, g_wEh); cudaGetSymbolAddress((void**)&wEl, g_wEl);
    cudaGetSymbolAddress((void**)&w0h, g_w0h); cudaGetSymbolAddress((void**)&w0l, g_w0l);
    cudaGetSymbolAddress((void**)&w1h, g_w1h); cudaGetSymbolAddress((void**)&w1l, g_w1l);
    cudaGetSymbolAddress((void**)&wPh, g_wPh); cudaGetSymbolAddress((void**)&wPl, g_wPl);

    const int SMEM = 1024 + 65536 + 32768 + 1280;   // 100608

    cudaFuncSetAttribute(k_mma<128, false, false, false, false>, cudaFuncAttributeMaxDynamicSharedMemorySize, SMEM);
    cudaFuncSetAttribute(k_mma<256, true,  true,  false, false>, cudaFuncAttributeMaxDynamicSharedMemorySize, SMEM);
    cudaFuncSetAttribute(k_mma<256, false, true,  true,  true >, cudaFuncAttributeMaxDynamicSharedMemorySize, SMEM);

    // side stream: CSR build + embeds + layer/pred W splits
    cudaStream_t s2;
    cudaStreamCreateWithFlags(&s2, cudaStreamNonBlocking);
    cudaEvent_t eFork, eJoin;
    cudaEventCreateWithFlags(&eFork, cudaEventDisableTiming);
    cudaEventCreateWithFlags(&eJoin, cudaEventDisableTiming);

    cudaEventRecord(eFork, 0);
    cudaStreamWaitEvent(s2, eFork, 0);

    cudaMemsetAsync(deg, 0, (size_t)NT * sizeof(int), s2);
    k_deg<<<(EPT + ETA + 255) / 256, 256, 0, s2>>>(src_pt, dst_pt, src_ta, dst_ta);
    k_alloc<<<(NT + 255) / 256, 256, 0, s2>>>();
    k_fill<<<(EPT + ETA + 255) / 256, 256, 0, s2>>>(src_pt, dst_pt, src_ta, dst_ta);
    k_embed2<<<((NPL + NAR) * 32 + 255) / 256, 256, 0, s2>>>(pl_ids, ar_ids, pl_table,
                                                             ar_table, type_tab, x);
    k_wsplit<256, true ><<<8, 256, 0, s2>>>(Wl0, Wr0, w0h, w0l);
    k_wsplit<256, true ><<<8, 256, 0, s2>>>(Wl1, Wr1, w1h, w1l);
    k_wsplit<256, false><<<8, 256, 0, s2>>>(Wp1, nullptr, wPh, wPl);
    cudaEventRecord(eJoin, s2);

    // main: encode W split + encode GEMM (track features -> x[OFF_TR..])
    k_wsplit<128, false><<<4, 256>>>(Wtr, nullptr, wEh, wEl);
    k_mma<128, false, false, false, false><<<GRID2, 256, SMEM>>>(
        track_x, nullptr, wEh, wEl, btr, type_tab + H,
        nullptr, nullptr, nullptr, nullptr, x + (size_t)OFF_TR * H, NTR);

    cudaStreamWaitEvent(0, eJoin, 0);

    // ---- layer 0 ----
    k_gather<<<(NT + 7) / 8, 256>>>(x, agg);
    k_mma<256, true, true, false, false><<<GRID2, 256, SMEM>>>(
        agg, x, w0h, w0l, bl0, nullptr,
        nullptr, nullptr, nullptr, nullptr, y, NT);

    // ---- layer 1 ----
    k_gather<<<(NT + 7) / 8, 256>>>(y, agg);
    k_mma<256, true, true, false, false><<<GRID2, 256, SMEM>>>(
        agg, y, w1h, w1l, bl1, nullptr,
        nullptr, nullptr, nullptr, nullptr, x, NT);

    // ---- predictor (gather + GEMM + dot fused) ----
    k_mma<256, false, true, true, true><<<GRID2, 256, SMEM>>>(
        nullptr, x, wPh, wPl, bp1, nullptr,
        lab_row, lab_col, Wp2, bp2, out, LBL);
}